// round 5
// baseline (speedup 1.0000x reference)
#include <cuda_runtime.h>
#include <math.h>

#define B_  8
#define T_  12
#define N_  1024
#define C_  64
#define D_  10
#define BT_ (B_*T_)   // 96

// ---------------- scratch (module globals; no runtime allocation) ----------
__device__ float g_supports[N_*N_];                 //  4 MB
__device__ float g_A[N_*N_];                        //  4 MB
__device__ float g_weights[N_*C_*C_];               // 16 MB
__device__ float g_bias[N_*C_];                     // 256 KB
__device__ float g_score[(size_t)BT_*N_*N_];        // 402 MB
__device__ float g_xg[(size_t)BT_*N_*C_];           // 25 MB

// ---------------- supports = I + relu(tanh(E1 E2^T - E2 E1^T)) -------------
__global__ void k_supports(const float* __restrict__ e1,
                           const float* __restrict__ e2) {
    int j = blockIdx.x * 16 + threadIdx.x;
    int i = blockIdx.y * 16 + threadIdx.y;
    float d = 0.f;
#pragma unroll
    for (int k = 0; k < D_; k++)
        d += e1[i*D_+k]*e2[j*D_+k] - e2[i*D_+k]*e1[j*D_+k];
    float v = fmaxf(tanhf(d), 0.f);
    if (i == j) v += 1.f;
    g_supports[i*N_ + j] = v;
}

// ---------------- A = row softmax of A_sym ----------------------------------
__global__ void k_softmaxA(const float* __restrict__ A_sym) {
    int row = blockIdx.x;
    int t = threadIdx.x;
    const float* r = A_sym + (size_t)row * N_;
    __shared__ float red[256];
    float vals[4];
    float m = -3.4e38f;
#pragma unroll
    for (int q = 0; q < 4; q++) { vals[q] = r[t + q*256]; m = fmaxf(m, vals[q]); }
    red[t] = m; __syncthreads();
    for (int s = 128; s > 0; s >>= 1) { if (t < s) red[t] = fmaxf(red[t], red[t+s]); __syncthreads(); }
    m = red[0]; __syncthreads();
    float sum = 0.f;
#pragma unroll
    for (int q = 0; q < 4; q++) { vals[q] = expf(vals[q] - m); sum += vals[q]; }
    red[t] = sum; __syncthreads();
    for (int s = 128; s > 0; s >>= 1) { if (t < s) red[t] += red[t+s]; __syncthreads(); }
    float inv = 1.f / red[0];
#pragma unroll
    for (int q = 0; q < 4; q++) g_A[(size_t)row*N_ + t + q*256] = vals[q] * inv;
}

// ---------------- generic 64x64x16 SGEMM body -------------------------------
// C[M x Ncols] = A[M x K] @ B[K x Ncols], all row-major, dims multiples of 64/16.
__device__ __forceinline__ void sgemm_body(const float* __restrict__ A,
                                           const float* __restrict__ Bm,
                                           float* __restrict__ Cm,
                                           int K, int Ncols) {
    __shared__ float As[16][68];
    __shared__ float Bs[16][68];
    int tid = threadIdx.x, tx = tid & 15, ty = tid >> 4;
    int m0 = blockIdx.y * 64, n0 = blockIdx.x * 64;
    float acc[4][4] = {};
    for (int k0 = 0; k0 < K; k0 += 16) {
#pragma unroll
        for (int e = tid; e < 1024; e += 256) {
            int mm = e >> 4, kk = e & 15;
            As[kk][mm] = A[(size_t)(m0+mm)*K + k0 + kk];
        }
#pragma unroll
        for (int e = tid; e < 1024; e += 256) {
            int kk = e >> 6, nn = e & 63;
            Bs[kk][nn] = Bm[(size_t)(k0+kk)*Ncols + n0 + nn];
        }
        __syncthreads();
#pragma unroll
        for (int k = 0; k < 16; k++) {
            float4 ra = *(const float4*)&As[k][ty<<2];
            float4 rb = *(const float4*)&Bs[k][tx<<2];
            float a[4] = {ra.x, ra.y, ra.z, ra.w};
            float b[4] = {rb.x, rb.y, rb.z, rb.w};
#pragma unroll
            for (int i = 0; i < 4; i++)
#pragma unroll
                for (int j = 0; j < 4; j++) acc[i][j] += a[i]*b[j];
        }
        __syncthreads();
    }
#pragma unroll
    for (int i = 0; i < 4; i++)
#pragma unroll
        for (int j = 0; j < 4; j++)
            Cm[(size_t)(m0+(ty<<2)+i)*Ncols + n0 + (tx<<2) + j] = acc[i][j];
}

__global__ void k_weights(const float* __restrict__ wp) {
    sgemm_body(g_supports, wp, g_weights, N_, C_*C_);
}
__global__ void k_biasg(const float* __restrict__ bp) {
    sgemm_body(g_supports, bp, g_bias, N_, C_);
}

// ---------------- dual GEMM: static branch + x_g share the x tile -----------
// out = gamma*relu(A @ x_bt);  g_xg = supports @ x_bt
__global__ void k_dual(const float* __restrict__ x,
                       const float* __restrict__ gamma,
                       float* __restrict__ out) {
    int bt = blockIdx.y;
    int m0 = blockIdx.x * 64;
    const float* X = x + (size_t)bt * N_ * C_;
    __shared__ float As[16][68], Ss[16][68], Xs[16][68];
    int tid = threadIdx.x, tx = tid & 15, ty = tid >> 4;
    float acc1[4][4] = {}, acc2[4][4] = {};
    for (int k0 = 0; k0 < N_; k0 += 16) {
#pragma unroll
        for (int e = tid; e < 1024; e += 256) {
            int mm = e >> 4, kk = e & 15;
            As[kk][mm] = g_A[(size_t)(m0+mm)*N_ + k0 + kk];
            Ss[kk][mm] = g_supports[(size_t)(m0+mm)*N_ + k0 + kk];
        }
#pragma unroll
        for (int e = tid; e < 1024; e += 256) {
            int kk = e >> 6, nn = e & 63;
            Xs[kk][nn] = X[(size_t)(k0+kk)*C_ + nn];
        }
        __syncthreads();
#pragma unroll
        for (int k = 0; k < 16; k++) {
            float4 ra = *(const float4*)&As[k][ty<<2];
            float4 rs = *(const float4*)&Ss[k][ty<<2];
            float4 rx = *(const float4*)&Xs[k][tx<<2];
            float a[4] = {ra.x, ra.y, ra.z, ra.w};
            float s[4] = {rs.x, rs.y, rs.z, rs.w};
            float b[4] = {rx.x, rx.y, rx.z, rx.w};
#pragma unroll
            for (int i = 0; i < 4; i++)
#pragma unroll
                for (int j = 0; j < 4; j++) {
                    acc1[i][j] += a[i]*b[j];
                    acc2[i][j] += s[i]*b[j];
                }
        }
        __syncthreads();
    }
    float g = gamma[0];
#pragma unroll
    for (int i = 0; i < 4; i++)
#pragma unroll
        for (int j = 0; j < 4; j++) {
            int n = m0 + (ty<<2) + i, c = (tx<<2) + j;
            size_t idx = ((size_t)bt*N_ + n)*C_ + c;
            out[idx]  = g * fmaxf(acc1[i][j], 0.f);
            g_xg[idx] = acc2[i][j];
        }
}

// ---------------- score = x x^T per (b,t) -----------------------------------
__global__ void k_score(const float* __restrict__ x) {
    int bt = blockIdx.z;
    int n0 = blockIdx.y * 64;
    int m0 = blockIdx.x * 64;
    const float* X = x + (size_t)bt * N_ * C_;
    __shared__ float As[16][68], Bs[16][68];
    int tid = threadIdx.x, tx = tid & 15, ty = tid >> 4;
    float acc[4][4] = {};
    for (int k0 = 0; k0 < C_; k0 += 16) {
#pragma unroll
        for (int e = tid; e < 1024; e += 256) {
            int r = e >> 4, kk = e & 15;
            As[kk][r] = X[(size_t)(n0+r)*C_ + k0 + kk];
            Bs[kk][r] = X[(size_t)(m0+r)*C_ + k0 + kk];
        }
        __syncthreads();
#pragma unroll
        for (int k = 0; k < 16; k++) {
            float4 ra = *(const float4*)&As[k][ty<<2];
            float4 rb = *(const float4*)&Bs[k][tx<<2];
            float a[4] = {ra.x, ra.y, ra.z, ra.w};
            float b[4] = {rb.x, rb.y, rb.z, rb.w};
#pragma unroll
            for (int i = 0; i < 4; i++)
#pragma unroll
                for (int j = 0; j < 4; j++) acc[i][j] += a[i]*b[j];
        }
        __syncthreads();
    }
    float* Sr = g_score + (size_t)bt * N_ * N_;
#pragma unroll
    for (int i = 0; i < 4; i++)
#pragma unroll
        for (int j = 0; j < 4; j++)
            Sr[(size_t)(n0+(ty<<2)+i)*N_ + m0 + (tx<<2) + j] = acc[i][j];
}

// ---------------- softmax over TIME axis, in place --------------------------
__global__ void k_softmax_t() {
    size_t idx = (size_t)blockIdx.x * blockDim.x + threadIdx.x;  // B*N*N threads
    int b = (int)(idx >> 20);              // N*N = 2^20
    size_t r = idx & ((size_t)N_*N_ - 1);
    size_t base = (size_t)b * T_ * N_ * N_ + r;
    float v[T_];
    float m = -3.4e38f;
#pragma unroll
    for (int t = 0; t < T_; t++) {
        v[t] = g_score[base + (size_t)t * N_ * N_];
        m = fmaxf(m, v[t]);
    }
    float sum = 0.f;
#pragma unroll
    for (int t = 0; t < T_; t++) { v[t] = expf(v[t] - m); sum += v[t]; }
    float inv = 1.f / sum;
#pragma unroll
    for (int t = 0; t < T_; t++)
        g_score[base + (size_t)t * N_ * N_] = v[t] * inv;
}

// ---------------- x_sa: out += beta * relu(P @ x_bt) ------------------------
__global__ void k_sa(const float* __restrict__ x,
                     const float* __restrict__ beta,
                     float* __restrict__ out) {
    int bt = blockIdx.y;
    int m0 = blockIdx.x * 64;
    const float* P = g_score + (size_t)bt * N_ * N_;
    const float* X = x + (size_t)bt * N_ * C_;
    __shared__ float As[16][68], Xs[16][68];
    int tid = threadIdx.x, tx = tid & 15, ty = tid >> 4;
    float acc[4][4] = {};
    for (int k0 = 0; k0 < N_; k0 += 16) {
#pragma unroll
        for (int e = tid; e < 1024; e += 256) {
            int mm = e >> 4, kk = e & 15;
            As[kk][mm] = P[(size_t)(m0+mm)*N_ + k0 + kk];
        }
#pragma unroll
        for (int e = tid; e < 1024; e += 256) {
            int kk = e >> 6, nn = e & 63;
            Xs[kk][nn] = X[(size_t)(k0+kk)*C_ + nn];
        }
        __syncthreads();
#pragma unroll
        for (int k = 0; k < 16; k++) {
            float4 ra = *(const float4*)&As[k][ty<<2];
            float4 rx = *(const float4*)&Xs[k][tx<<2];
            float a[4] = {ra.x, ra.y, ra.z, ra.w};
            float b[4] = {rx.x, rx.y, rx.z, rx.w};
#pragma unroll
            for (int i = 0; i < 4; i++)
#pragma unroll
                for (int j = 0; j < 4; j++) acc[i][j] += a[i]*b[j];
        }
        __syncthreads();
    }
    float be = beta[0];
#pragma unroll
    for (int i = 0; i < 4; i++)
#pragma unroll
        for (int j = 0; j < 4; j++) {
            int n = m0 + (ty<<2) + i, c = (tx<<2) + j;
            size_t idx = ((size_t)bt*N_ + n)*C_ + c;
            out[idx] += be * fmaxf(acc[i][j], 0.f);
        }
}

// ---------------- gconv: out += alpha*relu(xg[:,n,:] @ W[n] + bias[n]) ------
__global__ void k_gconv(const float* __restrict__ alpha,
                        float* __restrict__ out) {
    int n = blockIdx.x;
    int tid = threadIdx.x;
    __shared__ float Ws[64*64];
    __shared__ float Xs[96][64];
    __shared__ float bs[64];
#pragma unroll
    for (int e = tid; e < 4096; e += 256) Ws[e] = g_weights[(size_t)n*4096 + e];
    if (tid < 64) bs[tid] = g_bias[(size_t)n*64 + tid];
#pragma unroll
    for (int e = tid; e < 96*64; e += 256) {
        int r = e >> 6, c = e & 63;
        Xs[r][c] = g_xg[((size_t)r*N_ + n)*C_ + c];
    }
    __syncthreads();
    float al = alpha[0];
    int o = tid & 63, rg = tid >> 6;  // 4 row-groups x 64 outputs
    for (int r = rg; r < 96; r += 4) {
        float acc = bs[o];
#pragma unroll
        for (int i = 0; i < 64; i++) acc = fmaf(Xs[r][i], Ws[i*64 + o], acc);
        size_t idx = ((size_t)r*N_ + n)*C_ + o;
        out[idx] += al * fmaxf(acc, 0.f);
    }
}

// ---------------- launch ----------------------------------------------------
extern "C" void kernel_launch(void* const* d_in, const int* in_sizes, int n_in,
                              void* d_out, int out_size) {
    (void)in_sizes; (void)n_in; (void)out_size;
    const float* x     = (const float*)d_in[0];   // (B,T,N,C)
    const float* e1    = (const float*)d_in[1];   // (N,D)
    const float* e2    = (const float*)d_in[2];   // (N,D)
    const float* A_sym = (const float*)d_in[3];   // (N,N)
    const float* wp    = (const float*)d_in[4];   // (N,C,C)
    const float* bp    = (const float*)d_in[5];   // (N,C)
    const float* alpha = (const float*)d_in[6];
    const float* beta  = (const float*)d_in[7];
    const float* gamma = (const float*)d_in[8];
    float* out = (float*)d_out;

    k_supports<<<dim3(N_/16, N_/16), dim3(16,16)>>>(e1, e2);
    k_softmaxA<<<N_, 256>>>(A_sym);
    k_weights<<<dim3((C_*C_)/64, N_/64), 256>>>(wp);
    k_biasg  <<<dim3(C_/64,      N_/64), 256>>>(bp);
    k_dual   <<<dim3(N_/64, BT_), 256>>>(x, gamma, out);
    k_score  <<<dim3(N_/64, N_/64, BT_), 256>>>(x);
    k_softmax_t<<<(B_*N_*N_)/256, 256>>>();
    k_sa     <<<dim3(N_/64, BT_), 256>>>(x, beta, out);
    k_gconv  <<<N_, 256>>>(alpha, out);
}

// round 6
// speedup vs baseline: 1.3356x; 1.3356x over previous
#include <cuda_runtime.h>
#include <math.h>

#define B_  8
#define T_  12
#define N_  1024
#define C_  64
#define D_  10
#define BT_ (B_*T_)   // 96

typedef unsigned long long u64;

// ---------------- packed f32x2 helpers --------------------------------------
__device__ __forceinline__ u64 ffma2(u64 a, u64 b, u64 c) {
    u64 d; asm("fma.rn.f32x2 %0,%1,%2,%3;" : "=l"(d) : "l"(a), "l"(b), "l"(c));
    return d;
}
__device__ __forceinline__ u64 dup2(float x) {
    u64 d; unsigned r = __float_as_uint(x);
    asm("mov.b64 %0,{%1,%1};" : "=l"(d) : "r"(r));
    return d;
}
__device__ __forceinline__ float lo2(u64 v) { return __uint_as_float((unsigned)v); }
__device__ __forceinline__ float hi2(u64 v) { return __uint_as_float((unsigned)(v >> 32)); }

// ---------------- scratch (module globals; no runtime allocation) ----------
__device__ float g_supports[N_*N_];                 //  4 MB
__device__ float g_A[N_*N_];                        //  4 MB
__device__ float g_weights[N_*C_*C_];               // 16 MB
__device__ float g_bias[N_*C_];                     // 256 KB
__device__ float g_bias_part[8*N_*C_];              //  2 MB
__device__ float g_score[(size_t)BT_*N_*N_];        // 402 MB
__device__ float g_xg[(size_t)BT_*N_*C_];           // 25 MB

// ---------------- supports = I + relu(tanh(E1 E2^T - E2 E1^T)) -------------
__global__ void k_supports(const float* __restrict__ e1,
                           const float* __restrict__ e2) {
    int j = blockIdx.x * 16 + threadIdx.x;
    int i = blockIdx.y * 16 + threadIdx.y;
    float d = 0.f;
#pragma unroll
    for (int k = 0; k < D_; k++)
        d += e1[i*D_+k]*e2[j*D_+k] - e2[i*D_+k]*e1[j*D_+k];
    float v = fmaxf(tanhf(d), 0.f);
    if (i == j) v += 1.f;
    g_supports[i*N_ + j] = v;
}

// ---------------- A = row softmax of A_sym ----------------------------------
__global__ void k_softmaxA(const float* __restrict__ A_sym) {
    int row = blockIdx.x;
    int t = threadIdx.x;
    const float* r = A_sym + (size_t)row * N_;
    __shared__ float red[256];
    float vals[4];
    float m = -3.4e38f;
#pragma unroll
    for (int q = 0; q < 4; q++) { vals[q] = r[t + q*256]; m = fmaxf(m, vals[q]); }
    red[t] = m; __syncthreads();
    for (int s = 128; s > 0; s >>= 1) { if (t < s) red[t] = fmaxf(red[t], red[t+s]); __syncthreads(); }
    m = red[0]; __syncthreads();
    float sum = 0.f;
#pragma unroll
    for (int q = 0; q < 4; q++) { vals[q] = expf(vals[q] - m); sum += vals[q]; }
    red[t] = sum; __syncthreads();
    for (int s = 128; s > 0; s >>= 1) { if (t < s) red[t] += red[t+s]; __syncthreads(); }
    float inv = 1.f / red[0];
#pragma unroll
    for (int q = 0; q < 4; q++) g_A[(size_t)row*N_ + t + q*256] = vals[q] * inv;
}

// ============================================================================
// k_weights : g_weights[1024 x 4096] = supports[1024 x 1024] @ wp[1024 x 4096]
// 128x128 tile, 8i x 8j per thread, FFMA2 packed over i.
// ============================================================================
__global__ void __launch_bounds__(256, 2) k_weights(const float* __restrict__ wp) {
    const int m0 = blockIdx.y * 128;
    const int n0 = blockIdx.x * 128;
    __shared__ __align__(16) float As[16][132];   // transposed supports tile
    __shared__ __align__(16) float Bs[16][132];   // natural wp tile
    const int tid = threadIdx.x, tx = tid & 15, ty = tid >> 4;
    const int qq = tid & 3, mmb = tid >> 2;          // A loader: rows mmb, mmb+64
    const int bkk = tid >> 4, bnn = (tid & 15) * 4;  // B loader
    u64 acc[4][8];
#pragma unroll
    for (int i = 0; i < 4; i++)
#pragma unroll
        for (int j = 0; j < 8; j++) acc[i][j] = 0ull;

    float4 pa[2], pb[2];
#pragma unroll
    for (int p = 0; p < 2; p++)
        pa[p] = *(const float4*)&g_supports[(size_t)(m0+mmb+64*p)*N_ + 4*qq];
#pragma unroll
    for (int p = 0; p < 2; p++)
        pb[p] = *(const float4*)&wp[(size_t)bkk*4096 + n0 + bnn + 64*p];

    for (int k0 = 0; k0 < N_; k0 += 16) {
#pragma unroll
        for (int p = 0; p < 2; p++) {
            As[4*qq+0][mmb+64*p] = pa[p].x;
            As[4*qq+1][mmb+64*p] = pa[p].y;
            As[4*qq+2][mmb+64*p] = pa[p].z;
            As[4*qq+3][mmb+64*p] = pa[p].w;
            *(float4*)&Bs[bkk][bnn + 64*p] = pb[p];
        }
        __syncthreads();
        if (k0 + 16 < N_) {
#pragma unroll
            for (int p = 0; p < 2; p++)
                pa[p] = *(const float4*)&g_supports[(size_t)(m0+mmb+64*p)*N_ + k0+16 + 4*qq];
#pragma unroll
            for (int p = 0; p < 2; p++)
                pb[p] = *(const float4*)&wp[(size_t)(k0+16+bkk)*4096 + n0 + bnn + 64*p];
        }
#pragma unroll
        for (int k = 0; k < 16; k++) {
            const ulonglong2* ap = (const ulonglong2*)&As[k][ty*8];
            ulonglong2 A0 = ap[0], A1 = ap[1];
            u64 ar[4] = {A0.x, A0.y, A1.x, A1.y};
            float4 b0 = *(const float4*)&Bs[k][tx*8];
            float4 b1 = *(const float4*)&Bs[k][tx*8+4];
            u64 bd[8] = {dup2(b0.x), dup2(b0.y), dup2(b0.z), dup2(b0.w),
                         dup2(b1.x), dup2(b1.y), dup2(b1.z), dup2(b1.w)};
#pragma unroll
            for (int ip = 0; ip < 4; ip++)
#pragma unroll
                for (int j = 0; j < 8; j++)
                    acc[ip][j] = ffma2(ar[ip], bd[j], acc[ip][j]);
        }
        __syncthreads();
    }
#pragma unroll
    for (int ip = 0; ip < 4; ip++) {
        int r0 = m0 + ty*8 + 2*ip;
#pragma unroll
        for (int j = 0; j < 8; j++) {
            int c = n0 + tx*8 + j;
            g_weights[(size_t)r0*4096 + c]     = lo2(acc[ip][j]);
            g_weights[(size_t)(r0+1)*4096 + c] = hi2(acc[ip][j]);
        }
    }
}

// ============================================================================
// k_score : per (b,t)  score = X X^T   (X = x[bt] : 1024 x 64)
// 128x128 tile, 8i x 8j, K=64. Both operands transposed-loaded.
// ============================================================================
__global__ void __launch_bounds__(256, 2) k_score(const float* __restrict__ x) {
    const int bt = blockIdx.z;
    const int n0 = blockIdx.y * 128;   // rows of score
    const int m0 = blockIdx.x * 128;   // cols of score
    const float* X = x + (size_t)bt * N_ * C_;
    __shared__ __align__(16) float As[16][132];
    __shared__ __align__(16) float Bs[16][132];
    const int tid = threadIdx.x, tx = tid & 15, ty = tid >> 4;
    const int qq = tid & 3, mmb = tid >> 2;
    u64 acc[4][8];
#pragma unroll
    for (int i = 0; i < 4; i++)
#pragma unroll
        for (int j = 0; j < 8; j++) acc[i][j] = 0ull;

    float4 pa[2], pb[2];
#pragma unroll
    for (int p = 0; p < 2; p++) {
        pa[p] = *(const float4*)&X[(size_t)(n0+mmb+64*p)*C_ + 4*qq];
        pb[p] = *(const float4*)&X[(size_t)(m0+mmb+64*p)*C_ + 4*qq];
    }
    for (int k0 = 0; k0 < C_; k0 += 16) {
#pragma unroll
        for (int p = 0; p < 2; p++) {
            As[4*qq+0][mmb+64*p] = pa[p].x;
            As[4*qq+1][mmb+64*p] = pa[p].y;
            As[4*qq+2][mmb+64*p] = pa[p].z;
            As[4*qq+3][mmb+64*p] = pa[p].w;
            Bs[4*qq+0][mmb+64*p] = pb[p].x;
            Bs[4*qq+1][mmb+64*p] = pb[p].y;
            Bs[4*qq+2][mmb+64*p] = pb[p].z;
            Bs[4*qq+3][mmb+64*p] = pb[p].w;
        }
        __syncthreads();
        if (k0 + 16 < C_) {
#pragma unroll
            for (int p = 0; p < 2; p++) {
                pa[p] = *(const float4*)&X[(size_t)(n0+mmb+64*p)*C_ + k0+16 + 4*qq];
                pb[p] = *(const float4*)&X[(size_t)(m0+mmb+64*p)*C_ + k0+16 + 4*qq];
            }
        }
#pragma unroll
        for (int k = 0; k < 16; k++) {
            const ulonglong2* ap = (const ulonglong2*)&As[k][ty*8];
            ulonglong2 A0 = ap[0], A1 = ap[1];
            u64 ar[4] = {A0.x, A0.y, A1.x, A1.y};
            float4 b0 = *(const float4*)&Bs[k][tx*8];
            float4 b1 = *(const float4*)&Bs[k][tx*8+4];
            u64 bd[8] = {dup2(b0.x), dup2(b0.y), dup2(b0.z), dup2(b0.w),
                         dup2(b1.x), dup2(b1.y), dup2(b1.z), dup2(b1.w)};
#pragma unroll
            for (int ip = 0; ip < 4; ip++)
#pragma unroll
                for (int j = 0; j < 8; j++)
                    acc[ip][j] = ffma2(ar[ip], bd[j], acc[ip][j]);
        }
        __syncthreads();
    }
    float* Sr = g_score + (size_t)bt * N_ * N_;
#pragma unroll
    for (int ip = 0; ip < 4; ip++) {
        int r0 = n0 + ty*8 + 2*ip;
#pragma unroll
        for (int j = 0; j < 8; j++) {
            int c = m0 + tx*8 + j;
            Sr[(size_t)r0*N_ + c]     = lo2(acc[ip][j]);
            Sr[(size_t)(r0+1)*N_ + c] = hi2(acc[ip][j]);
        }
    }
}

// ============================================================================
// k_dual : out = gamma*relu(g_A @ X) ; g_xg = g_supports @ X   per (b,t)
// 128x64 tile, dual A-operands sharing the X tile. 8i x 4j x 2 per thread.
// ============================================================================
__global__ void __launch_bounds__(256, 2) k_dual(const float* __restrict__ x,
                                                 const float* __restrict__ gamma,
                                                 float* __restrict__ out) {
    const int bt = blockIdx.y;
    const int m0 = blockIdx.x * 128;
    const float* X = x + (size_t)bt * N_ * C_;
    __shared__ __align__(16) float As1[16][132];
    __shared__ __align__(16) float As2[16][132];
    __shared__ __align__(16) float Bs[16][64];
    const int tid = threadIdx.x, tx = tid & 15, ty = tid >> 4;
    const int qq = tid & 3, mmb = tid >> 2;
    const int bkk = tid >> 4, bnn = (tid & 15) * 4;
    u64 acc1[4][4], acc2[4][4];
#pragma unroll
    for (int i = 0; i < 4; i++)
#pragma unroll
        for (int j = 0; j < 4; j++) { acc1[i][j] = 0ull; acc2[i][j] = 0ull; }

    float4 p1[2], p2[2], pb;
#pragma unroll
    for (int p = 0; p < 2; p++) {
        p1[p] = *(const float4*)&g_A[(size_t)(m0+mmb+64*p)*N_ + 4*qq];
        p2[p] = *(const float4*)&g_supports[(size_t)(m0+mmb+64*p)*N_ + 4*qq];
    }
    pb = *(const float4*)&X[(size_t)bkk*C_ + bnn];

    for (int k0 = 0; k0 < N_; k0 += 16) {
#pragma unroll
        for (int p = 0; p < 2; p++) {
            As1[4*qq+0][mmb+64*p] = p1[p].x;
            As1[4*qq+1][mmb+64*p] = p1[p].y;
            As1[4*qq+2][mmb+64*p] = p1[p].z;
            As1[4*qq+3][mmb+64*p] = p1[p].w;
            As2[4*qq+0][mmb+64*p] = p2[p].x;
            As2[4*qq+1][mmb+64*p] = p2[p].y;
            As2[4*qq+2][mmb+64*p] = p2[p].z;
            As2[4*qq+3][mmb+64*p] = p2[p].w;
        }
        *(float4*)&Bs[bkk][bnn] = pb;
        __syncthreads();
        if (k0 + 16 < N_) {
#pragma unroll
            for (int p = 0; p < 2; p++) {
                p1[p] = *(const float4*)&g_A[(size_t)(m0+mmb+64*p)*N_ + k0+16 + 4*qq];
                p2[p] = *(const float4*)&g_supports[(size_t)(m0+mmb+64*p)*N_ + k0+16 + 4*qq];
            }
            pb = *(const float4*)&X[(size_t)(k0+16+bkk)*C_ + bnn];
        }
#pragma unroll
        for (int k = 0; k < 16; k++) {
            const ulonglong2* a1p = (const ulonglong2*)&As1[k][ty*8];
            const ulonglong2* a2p = (const ulonglong2*)&As2[k][ty*8];
            ulonglong2 A10 = a1p[0], A11 = a1p[1];
            ulonglong2 A20 = a2p[0], A21 = a2p[1];
            u64 a1r[4] = {A10.x, A10.y, A11.x, A11.y};
            u64 a2r[4] = {A20.x, A20.y, A21.x, A21.y};
            float4 bq = *(const float4*)&Bs[k][tx*4];
            u64 bd[4] = {dup2(bq.x), dup2(bq.y), dup2(bq.z), dup2(bq.w)};
#pragma unroll
            for (int ip = 0; ip < 4; ip++)
#pragma unroll
                for (int j = 0; j < 4; j++) {
                    acc1[ip][j] = ffma2(a1r[ip], bd[j], acc1[ip][j]);
                    acc2[ip][j] = ffma2(a2r[ip], bd[j], acc2[ip][j]);
                }
        }
        __syncthreads();
    }
    const float g = gamma[0];
#pragma unroll
    for (int ip = 0; ip < 4; ip++) {
        int r0 = m0 + ty*8 + 2*ip;
#pragma unroll
        for (int j = 0; j < 4; j++) {
            int c = tx*4 + j;
            size_t i0 = ((size_t)bt*N_ + r0)*C_ + c;
            out[i0]      = g * fmaxf(lo2(acc1[ip][j]), 0.f);
            out[i0+C_]   = g * fmaxf(hi2(acc1[ip][j]), 0.f);
            g_xg[i0]     = lo2(acc2[ip][j]);
            g_xg[i0+C_]  = hi2(acc2[ip][j]);
        }
    }
}

// ---------------- softmax over TIME axis, in place --------------------------
__global__ void k_softmax_t() {
    size_t idx = (size_t)blockIdx.x * blockDim.x + threadIdx.x;  // B*N*N threads
    int b = (int)(idx >> 20);              // N*N = 2^20
    size_t r = idx & ((size_t)N_*N_ - 1);
    size_t base = (size_t)b * T_ * N_ * N_ + r;
    float v[T_];
    float m = -3.4e38f;
#pragma unroll
    for (int t = 0; t < T_; t++) {
        v[t] = g_score[base + (size_t)t * N_ * N_];
        m = fmaxf(m, v[t]);
    }
    float sum = 0.f;
#pragma unroll
    for (int t = 0; t < T_; t++) { v[t] = expf(v[t] - m); sum += v[t]; }
    float inv = 1.f / sum;
#pragma unroll
    for (int t = 0; t < T_; t++)
        g_score[base + (size_t)t * N_ * N_] = v[t] * inv;
}

// ============================================================================
// k_sa : out += beta * relu(P @ X)   per (b,t)
// 256x64 tile, 16i x 4j per thread, FFMA2.
// ============================================================================
__global__ void __launch_bounds__(256, 2) k_sa(const float* __restrict__ x,
                                               const float* __restrict__ beta,
                                               float* __restrict__ out) {
    const int bt = blockIdx.y;
    const int m0 = blockIdx.x * 256;
    const float* P = g_score + (size_t)bt * N_ * N_;
    const float* X = x + (size_t)bt * N_ * C_;
    __shared__ __align__(16) float As[16][260];
    __shared__ __align__(16) float Bs[16][64];
    const int tid = threadIdx.x, tx = tid & 15, ty = tid >> 4;
    const int qq = tid & 3, mmb = tid >> 2;          // rows mmb + 64p, p=0..3
    const int bkk = tid >> 4, bnn = (tid & 15) * 4;
    u64 acc[8][4];
#pragma unroll
    for (int i = 0; i < 8; i++)
#pragma unroll
        for (int j = 0; j < 4; j++) acc[i][j] = 0ull;

    float4 pa[4], pb;
#pragma unroll
    for (int p = 0; p < 4; p++)
        pa[p] = *(const float4*)&P[(size_t)(m0+mmb+64*p)*N_ + 4*qq];
    pb = *(const float4*)&X[(size_t)bkk*C_ + bnn];

    for (int k0 = 0; k0 < N_; k0 += 16) {
#pragma unroll
        for (int p = 0; p < 4; p++) {
            As[4*qq+0][mmb+64*p] = pa[p].x;
            As[4*qq+1][mmb+64*p] = pa[p].y;
            As[4*qq+2][mmb+64*p] = pa[p].z;
            As[4*qq+3][mmb+64*p] = pa[p].w;
        }
        *(float4*)&Bs[bkk][bnn] = pb;
        __syncthreads();
        if (k0 + 16 < N_) {
#pragma unroll
            for (int p = 0; p < 4; p++)
                pa[p] = *(const float4*)&P[(size_t)(m0+mmb+64*p)*N_ + k0+16 + 4*qq];
            pb = *(const float4*)&X[(size_t)(k0+16+bkk)*C_ + bnn];
        }
#pragma unroll
        for (int k = 0; k < 16; k++) {
            const ulonglong2* ap = (const ulonglong2*)&As[k][ty*16];
            ulonglong2 A0 = ap[0], A1 = ap[1], A2 = ap[2], A3 = ap[3];
            u64 ar[8] = {A0.x, A0.y, A1.x, A1.y, A2.x, A2.y, A3.x, A3.y};
            float4 bq = *(const float4*)&Bs[k][tx*4];
            u64 bd[4] = {dup2(bq.x), dup2(bq.y), dup2(bq.z), dup2(bq.w)};
#pragma unroll
            for (int ip = 0; ip < 8; ip++)
#pragma unroll
                for (int j = 0; j < 4; j++)
                    acc[ip][j] = ffma2(ar[ip], bd[j], acc[ip][j]);
        }
        __syncthreads();
    }
    const float be = beta[0];
#pragma unroll
    for (int ip = 0; ip < 8; ip++) {
        int r0 = m0 + ty*16 + 2*ip;
#pragma unroll
        for (int j = 0; j < 4; j++) {
            int c = tx*4 + j;
            size_t i0 = ((size_t)bt*N_ + r0)*C_ + c;
            out[i0]    += be * fmaxf(lo2(acc[ip][j]), 0.f);
            out[i0+C_] += be * fmaxf(hi2(acc[ip][j]), 0.f);
        }
    }
}

// ============================================================================
// bias = supports @ bias_pool, split-K into 8 chunks + reduce
// ============================================================================
__global__ void k_bias_part(const float* __restrict__ bp) {
    __shared__ float As[16][68];
    __shared__ float Bs[16][68];
    int tid = threadIdx.x, tx = tid & 15, ty = tid >> 4;
    int m0 = blockIdx.x * 64;
    int kb = blockIdx.y * 128;
    float acc[4][4] = {};
    for (int k0 = kb; k0 < kb + 128; k0 += 16) {
#pragma unroll
        for (int e = tid; e < 1024; e += 256) {
            int mm = e >> 4, kk = e & 15;
            As[kk][mm] = g_supports[(size_t)(m0+mm)*N_ + k0 + kk];
        }
#pragma unroll
        for (int e = tid; e < 1024; e += 256) {
            int kk = e >> 6, nn = e & 63;
            Bs[kk][nn] = bp[(size_t)(k0+kk)*C_ + nn];
        }
        __syncthreads();
#pragma unroll
        for (int k = 0; k < 16; k++) {
            float4 ra = *(const float4*)&As[k][ty<<2];
            float4 rb = *(const float4*)&Bs[k][tx<<2];
            float a[4] = {ra.x, ra.y, ra.z, ra.w};
            float b[4] = {rb.x, rb.y, rb.z, rb.w};
#pragma unroll
            for (int i = 0; i < 4; i++)
#pragma unroll
                for (int j = 0; j < 4; j++) acc[i][j] += a[i]*b[j];
        }
        __syncthreads();
    }
    float* dst = g_bias_part + (size_t)blockIdx.y * N_ * C_;
#pragma unroll
    for (int i = 0; i < 4; i++)
#pragma unroll
        for (int j = 0; j < 4; j++)
            dst[(size_t)(m0+(ty<<2)+i)*C_ + (tx<<2) + j] = acc[i][j];
}

__global__ void k_bias_red() {
    int i = blockIdx.x * 256 + threadIdx.x;
    float s = 0.f;
#pragma unroll
    for (int c = 0; c < 8; c++) s += g_bias_part[(size_t)c*N_*C_ + i];
    g_bias[i] = s;
}

// ---------------- gconv: out += alpha*relu(xg[:,n,:] @ W[n] + bias[n]) ------
__global__ void k_gconv(const float* __restrict__ alpha,
                        float* __restrict__ out) {
    int n = blockIdx.x;
    int tid = threadIdx.x;
    __shared__ float Ws[64*64];
    __shared__ float Xs[96][64];
    __shared__ float bs[64];
#pragma unroll
    for (int e = tid; e < 4096; e += 256) Ws[e] = g_weights[(size_t)n*4096 + e];
    if (tid < 64) bs[tid] = g_bias[(size_t)n*64 + tid];
#pragma unroll
    for (int e = tid; e < 96*64; e += 256) {
        int r = e >> 6, c = e & 63;
        Xs[r][c] = g_xg[((size_t)r*N_ + n)*C_ + c];
    }
    __syncthreads();
    float al = alpha[0];
    int o = tid & 63, rg = tid >> 6;
    for (int r = rg; r < 96; r += 4) {
        float acc = bs[o];
#pragma unroll
        for (int i = 0; i < 64; i++) acc = fmaf(Xs[r][i], Ws[i*64 + o], acc);
        size_t idx = ((size_t)r*N_ + n)*C_ + o;
        out[idx] += al * fmaxf(acc, 0.f);
    }
}

// ---------------- launch ----------------------------------------------------
extern "C" void kernel_launch(void* const* d_in, const int* in_sizes, int n_in,
                              void* d_out, int out_size) {
    (void)in_sizes; (void)n_in; (void)out_size;
    const float* x     = (const float*)d_in[0];   // (B,T,N,C)
    const float* e1    = (const float*)d_in[1];   // (N,D)
    const float* e2    = (const float*)d_in[2];   // (N,D)
    const float* A_sym = (const float*)d_in[3];   // (N,N)
    const float* wp    = (const float*)d_in[4];   // (N,C,C)
    const float* bp    = (const float*)d_in[5];   // (N,C)
    const float* alpha = (const float*)d_in[6];
    const float* beta  = (const float*)d_in[7];
    const float* gamma = (const float*)d_in[8];
    float* out = (float*)d_out;

    k_supports  <<<dim3(N_/16, N_/16), dim3(16,16)>>>(e1, e2);
    k_softmaxA  <<<N_, 256>>>(A_sym);
    k_weights   <<<dim3((C_*C_)/128, N_/128), 256>>>(wp);
    k_bias_part <<<dim3(N_/64, 8), 256>>>(bp);
    k_bias_red  <<<(N_*C_)/256, 256>>>();
    k_dual      <<<dim3(N_/128, BT_), 256>>>(x, gamma, out);
    k_score     <<<dim3(N_/128, N_/128, BT_), 256>>>(x);
    k_softmax_t <<<(B_*N_*N_)/256, 256>>>();
    k_sa        <<<dim3(N_/256, BT_), 256>>>(x, beta, out);
    k_gconv     <<<N_, 256>>>(alpha, out);
}

// round 8
// speedup vs baseline: 2.4919x; 1.8657x over previous
#include <cuda_runtime.h>
#include <cuda_bf16.h>
#include <math.h>
#include <stdint.h>

#define B_  8
#define T_  12
#define N_  1024
#define C_  64
#define D_  10
#define BT_ (B_*T_)   // 96

// ======================= mma.sync / ldmatrix helpers ========================
__device__ __forceinline__ uint32_t sm_addr(const void* p) {
    return (uint32_t)__cvta_generic_to_shared(p);
}
__device__ __forceinline__ void ldsm_x4(unsigned* r, uint32_t a) {
    asm volatile("ldmatrix.sync.aligned.m8n8.x4.shared.b16 {%0,%1,%2,%3}, [%4];"
                 : "=r"(r[0]), "=r"(r[1]), "=r"(r[2]), "=r"(r[3]) : "r"(a));
}
__device__ __forceinline__ void ldsm_x4t(unsigned* r, uint32_t a) {
    asm volatile("ldmatrix.sync.aligned.m8n8.x4.trans.shared.b16 {%0,%1,%2,%3}, [%4];"
                 : "=r"(r[0]), "=r"(r[1]), "=r"(r[2]), "=r"(r[3]) : "r"(a));
}
__device__ __forceinline__ void mma16816(float* d, const unsigned* a, const unsigned* b) {
    asm volatile("mma.sync.aligned.m16n8k16.row.col.f32.bf16.bf16.f32 "
                 "{%0,%1,%2,%3}, {%4,%5,%6,%7}, {%8,%9}, {%0,%1,%2,%3};"
                 : "+f"(d[0]), "+f"(d[1]), "+f"(d[2]), "+f"(d[3])
                 : "r"(a[0]), "r"(a[1]), "r"(a[2]), "r"(a[3]),
                   "r"(b[0]), "r"(b[1]));
}
__device__ __forceinline__ void split_bf16(float v, __nv_bfloat16& h, __nv_bfloat16& l) {
    h = __float2bfloat16(v);
    l = __float2bfloat16(v - __bfloat162float(h));
}

// stage rows x (COLS8*8) bf16 tile gmem->smem (padded pitch, 16B vectors)
template<int COLS8>
__device__ __forceinline__ void stage(__nv_bfloat16* s, int pitch,
                                      const __nv_bfloat16* __restrict__ g,
                                      size_t gstride, int rows) {
    int tot = rows * COLS8;
    for (int i = threadIdx.x; i < tot; i += blockDim.x) {
        int r = i / COLS8, c = (i % COLS8) * 8;
        *(uint4*)(s + r*pitch + c) = *(const uint4*)(g + (size_t)r*gstride + c);
    }
}

// warp-level split-bf16 MMA over one 64-K chunk.
// MI m-tiles of 16 (warp M = MI*16), warp N = 32 (4 n-tiles of 8).
template<int MI>
__device__ __forceinline__ void warp_mma(float (&acc)[MI][4][4],
        const __nv_bfloat16* Ah, const __nv_bfloat16* Al, int pa,
        const __nv_bfloat16* Bh, const __nv_bfloat16* Bl, int pb,
        int m_base, int n_base, int lane) {
    const int ar = lane & 15, ac = (lane >> 4) * 8;
#pragma unroll
    for (int ks = 0; ks < 4; ks++) {
        unsigned ah[MI][4], al[MI][4], bh[2][4], bl[2][4];
#pragma unroll
        for (int mi = 0; mi < MI; mi++) {
            int off = (m_base + mi*16 + ar)*pa + ks*16 + ac;
            ldsm_x4(ah[mi], sm_addr(Ah + off));
            ldsm_x4(al[mi], sm_addr(Al + off));
        }
#pragma unroll
        for (int njp = 0; njp < 2; njp++) {
            int off = (ks*16 + ar)*pb + n_base + njp*16 + ac;
            ldsm_x4t(bh[njp], sm_addr(Bh + off));
            ldsm_x4t(bl[njp], sm_addr(Bl + off));
        }
#pragma unroll
        for (int mi = 0; mi < MI; mi++)
#pragma unroll
            for (int j = 0; j < 4; j++) {
                const unsigned* ph = &bh[j>>1][(j&1)*2];
                const unsigned* pl = &bl[j>>1][(j&1)*2];
                mma16816(acc[mi][j], ah[mi], ph);
                mma16816(acc[mi][j], ah[mi], pl);
                mma16816(acc[mi][j], al[mi], ph);
            }
    }
}

// ======================= scratch globals ====================================
__device__ float         g_supports[N_*N_];
__device__ __nv_bfloat16 g_sup_hi[N_*N_], g_sup_lo[N_*N_];
__device__ __nv_bfloat16 g_A_hi[N_*N_],   g_A_lo[N_*N_];
__device__ __nv_bfloat16 g_x_hi[(size_t)BT_*N_*C_],  g_x_lo[(size_t)BT_*N_*C_];
__device__ __nv_bfloat16 g_xT_hi[(size_t)BT_*C_*N_], g_xT_lo[(size_t)BT_*C_*N_];
__device__ __nv_bfloat16 g_wp_hi[(size_t)1024*4096], g_wp_lo[(size_t)1024*4096];
__device__ float         g_weights[N_*C_*C_];
__device__ float         g_bias[N_*C_];
__device__ float         g_bias_part[8*N_*C_];
__device__ float         g_score[(size_t)BT_*N_*N_];
__device__ __nv_bfloat16 g_P_hi[(size_t)BT_*N_*N_], g_P_lo[(size_t)BT_*N_*N_];
__device__ float         g_xg[(size_t)BT_*N_*C_];

// ======================= small kernels ======================================
__global__ void k_supports(const float* __restrict__ e1,
                           const float* __restrict__ e2) {
    int j = blockIdx.x * 16 + threadIdx.x;
    int i = blockIdx.y * 16 + threadIdx.y;
    float d = 0.f;
#pragma unroll
    for (int k = 0; k < D_; k++)
        d += e1[i*D_+k]*e2[j*D_+k] - e2[i*D_+k]*e1[j*D_+k];
    float v = fmaxf(tanhf(d), 0.f);
    if (i == j) v += 1.f;
    g_supports[i*N_ + j] = v;
    __nv_bfloat16 h, l; split_bf16(v, h, l);
    g_sup_hi[i*N_ + j] = h; g_sup_lo[i*N_ + j] = l;
}

__global__ void k_softmaxA(const float* __restrict__ A_sym) {
    int row = blockIdx.x, t = threadIdx.x;
    const float* r = A_sym + (size_t)row * N_;
    __shared__ float red[256];
    float vals[4]; float m = -3.4e38f;
#pragma unroll
    for (int q = 0; q < 4; q++) { vals[q] = r[t + q*256]; m = fmaxf(m, vals[q]); }
    red[t] = m; __syncthreads();
    for (int s = 128; s > 0; s >>= 1) { if (t < s) red[t] = fmaxf(red[t], red[t+s]); __syncthreads(); }
    m = red[0]; __syncthreads();
    float sum = 0.f;
#pragma unroll
    for (int q = 0; q < 4; q++) { vals[q] = expf(vals[q] - m); sum += vals[q]; }
    red[t] = sum; __syncthreads();
    for (int s = 128; s > 0; s >>= 1) { if (t < s) red[t] += red[t+s]; __syncthreads(); }
    float inv = 1.f / red[0];
#pragma unroll
    for (int q = 0; q < 4; q++) {
        float v = vals[q] * inv;
        __nv_bfloat16 h, l; split_bf16(v, h, l);
        size_t idx = (size_t)row*N_ + t + q*256;
        g_A_hi[idx] = h; g_A_lo[idx] = l;
    }
}

// x -> x_hi/lo (bt,n,c) and xT_hi/lo (bt,c,n)
__global__ void k_cvt_x(const float* __restrict__ x) {
    int bt = blockIdx.y, n0 = blockIdx.x * 64;
    __shared__ float tbuf[64][65];
    int tid = threadIdx.x;
    for (int e = tid; e < 4096; e += 256) {
        int n = e >> 6, c = e & 63;
        float v = x[((size_t)bt*N_ + n0 + n)*C_ + c];
        tbuf[n][c] = v;
        __nv_bfloat16 h, l; split_bf16(v, h, l);
        size_t idx = ((size_t)bt*N_ + n0 + n)*C_ + c;
        g_x_hi[idx] = h; g_x_lo[idx] = l;
    }
    __syncthreads();
    for (int e = tid; e < 4096; e += 256) {
        int c = e >> 6, n = e & 63;
        float v = tbuf[n][c];
        __nv_bfloat16 h, l; split_bf16(v, h, l);
        size_t idx = ((size_t)bt*C_ + c)*N_ + n0 + n;
        g_xT_hi[idx] = h; g_xT_lo[idx] = l;
    }
}

// wp (1024 x 4096) fp32 -> hi/lo bf16, same layout (k-major, as mma.sync wants)
__global__ void k_cvt_wp(const float* __restrict__ wp) {
    size_t i = ((size_t)blockIdx.x*256 + threadIdx.x)*4;
    float4 v = *(const float4*)(wp + i);
    __nv_bfloat16 h, l;
    split_bf16(v.x, h, l); g_wp_hi[i+0] = h; g_wp_lo[i+0] = l;
    split_bf16(v.y, h, l); g_wp_hi[i+1] = h; g_wp_lo[i+1] = l;
    split_bf16(v.z, h, l); g_wp_hi[i+2] = h; g_wp_lo[i+2] = l;
    split_bf16(v.w, h, l); g_wp_hi[i+3] = h; g_wp_lo[i+3] = l;
}

// ======================= MMA GEMM kernels ===================================
// smem elem offsets for the 128x128 kernels (pitches: A=72, B=136)
#define OW_AH 0
#define OW_AL 9216
#define OW_BH 18432
#define OW_BL 27136
#define SMW_BYTES ((27136 + 8704) * 2)   // 71680

// ---- weights: g_weights[n][io] = sum_d S[n][d] wp[d][io] -------------------
__global__ void __launch_bounds__(256) k_weights_mma() {
    extern __shared__ __nv_bfloat16 sm[];
    const int n0 = blockIdx.y * 128, io0 = blockIdx.x * 128;
    const int tid = threadIdx.x, wid = tid >> 5, lane = tid & 31;
    const int m_base = (wid >> 2) * 64, n_base = (wid & 3) * 32;
    float acc[4][4][4] = {};
    for (int ch = 0; ch < 16; ch++) {
        int ko = ch * 64;
        stage<8> (sm+OW_AH,  72, g_sup_hi + (size_t)n0*N_ + ko, N_, 128);
        stage<8> (sm+OW_AL,  72, g_sup_lo + (size_t)n0*N_ + ko, N_, 128);
        stage<16>(sm+OW_BH, 136, g_wp_hi + (size_t)ko*4096 + io0, 4096, 64);
        stage<16>(sm+OW_BL, 136, g_wp_lo + (size_t)ko*4096 + io0, 4096, 64);
        __syncthreads();
        warp_mma<4>(acc, sm+OW_AH, sm+OW_AL, 72, sm+OW_BH, sm+OW_BL, 136,
                    m_base, n_base, lane);
        __syncthreads();
    }
#pragma unroll
    for (int mi = 0; mi < 4; mi++)
#pragma unroll
        for (int j = 0; j < 4; j++) {
            int r = n0 + m_base + mi*16 + (lane >> 2);
            int c = io0 + n_base + j*8 + (lane & 3)*2;
            g_weights[(size_t)r*4096 + c]       = acc[mi][j][0];
            g_weights[(size_t)r*4096 + c + 1]   = acc[mi][j][1];
            g_weights[(size_t)(r+8)*4096 + c]   = acc[mi][j][2];
            g_weights[(size_t)(r+8)*4096 + c+1] = acc[mi][j][3];
        }
}

// ---- score: score[bt][n][m] = sum_c x[n][c] x[m][c], K = 64 ----------------
__global__ void __launch_bounds__(256) k_score_mma() {
    extern __shared__ __nv_bfloat16 sm[];
    const int bt = blockIdx.z, n0 = blockIdx.y * 128, m0 = blockIdx.x * 128;
    const int tid = threadIdx.x, wid = tid >> 5, lane = tid & 31;
    const int m_base = (wid >> 2) * 64, n_base = (wid & 3) * 32;
    float acc[4][4][4] = {};
    stage<8> (sm+OW_AH,  72, g_x_hi + ((size_t)bt*N_ + n0)*C_, C_, 128);
    stage<8> (sm+OW_AL,  72, g_x_lo + ((size_t)bt*N_ + n0)*C_, C_, 128);
    stage<16>(sm+OW_BH, 136, g_xT_hi + (size_t)bt*C_*N_ + m0, N_, 64);
    stage<16>(sm+OW_BL, 136, g_xT_lo + (size_t)bt*C_*N_ + m0, N_, 64);
    __syncthreads();
    warp_mma<4>(acc, sm+OW_AH, sm+OW_AL, 72, sm+OW_BH, sm+OW_BL, 136,
                m_base, n_base, lane);
    float* S = g_score + (size_t)bt*N_*N_;
#pragma unroll
    for (int mi = 0; mi < 4; mi++)
#pragma unroll
        for (int j = 0; j < 4; j++) {
            int r = n0 + m_base + mi*16 + (lane >> 2);
            int c = m0 + n_base + j*8 + (lane & 3)*2;
            S[(size_t)r*N_ + c]       = acc[mi][j][0];
            S[(size_t)r*N_ + c + 1]   = acc[mi][j][1];
            S[(size_t)(r+8)*N_ + c]   = acc[mi][j][2];
            S[(size_t)(r+8)*N_ + c+1] = acc[mi][j][3];
        }
}

// ---- softmax over T, writes split-bf16 P -----------------------------------
__global__ void k_softmax_t() {
    size_t idx = (size_t)blockIdx.x * blockDim.x + threadIdx.x;
    int b = (int)(idx >> 20);
    size_t r = idx & ((size_t)N_*N_ - 1);
    size_t base = (size_t)b * T_ * N_ * N_ + r;
    float v[T_]; float m = -3.4e38f;
#pragma unroll
    for (int t = 0; t < T_; t++) {
        v[t] = g_score[base + (size_t)t * N_ * N_];
        m = fmaxf(m, v[t]);
    }
    float sum = 0.f;
#pragma unroll
    for (int t = 0; t < T_; t++) { v[t] = expf(v[t] - m); sum += v[t]; }
    float inv = 1.f / sum;
#pragma unroll
    for (int t = 0; t < T_; t++) {
        float p = v[t] * inv;
        __nv_bfloat16 h, l; split_bf16(p, h, l);
        size_t o = base + (size_t)t * N_ * N_;
        g_P_hi[o] = h; g_P_lo[o] = l;
    }
}

// ---- sa: out += beta * relu(P @ X) per bt. block 128x64, warp 32x32 --------
#define OS_AH 0
#define OS_AL 9216
#define OS_BH 18432
#define OS_BL 23040
#define SMS_BYTES ((23040 + 4608) * 2)   // 55296

__global__ void __launch_bounds__(256) k_sa_mma(const float* __restrict__ beta,
                                                float* __restrict__ out) {
    extern __shared__ __nv_bfloat16 sm[];
    const int bt = blockIdx.y, r0 = blockIdx.x * 128;
    const int tid = threadIdx.x, wid = tid >> 5, lane = tid & 31;
    const int m_base = (wid >> 1) * 32, n_base = (wid & 1) * 32;
    float acc[2][4][4] = {};
    for (int ch = 0; ch < 16; ch++) {
        int ko = ch * 64;
        stage<8>(sm+OS_AH, 72, g_P_hi + ((size_t)bt*N_ + r0)*N_ + ko, N_, 128);
        stage<8>(sm+OS_AL, 72, g_P_lo + ((size_t)bt*N_ + r0)*N_ + ko, N_, 128);
        stage<8>(sm+OS_BH, 72, g_x_hi + ((size_t)bt*N_ + ko)*C_, C_, 64);
        stage<8>(sm+OS_BL, 72, g_x_lo + ((size_t)bt*N_ + ko)*C_, C_, 64);
        __syncthreads();
        warp_mma<2>(acc, sm+OS_AH, sm+OS_AL, 72, sm+OS_BH, sm+OS_BL, 72,
                    m_base, n_base, lane);
        __syncthreads();
    }
    const float be = beta[0];
#pragma unroll
    for (int mi = 0; mi < 2; mi++)
#pragma unroll
        for (int j = 0; j < 4; j++) {
            int r = r0 + m_base + mi*16 + (lane >> 2);
            int c = n_base + j*8 + (lane & 3)*2;
            size_t i0 = ((size_t)bt*N_ + r)*C_ + c;
            size_t i8 = ((size_t)bt*N_ + r + 8)*C_ + c;
            out[i0]   += be * fmaxf(acc[mi][j][0], 0.f);
            out[i0+1] += be * fmaxf(acc[mi][j][1], 0.f);
            out[i8]   += be * fmaxf(acc[mi][j][2], 0.f);
            out[i8+1] += be * fmaxf(acc[mi][j][3], 0.f);
        }
}

// ---- dual: out = gamma*relu(A@X) ; xg = S@X.  block 128x64 -----------------
#define OD_A1H 0
#define OD_A1L 9216
#define OD_A2H 18432
#define OD_A2L 27648
#define OD_BH  36864
#define OD_BL  41472
#define SMD_BYTES ((41472 + 4608) * 2)   // 92160

__global__ void __launch_bounds__(256) k_dual_mma(const float* __restrict__ gamma,
                                                  float* __restrict__ out) {
    extern __shared__ __nv_bfloat16 sm[];
    const int bt = blockIdx.y, r0 = blockIdx.x * 128;
    const int tid = threadIdx.x, wid = tid >> 5, lane = tid & 31;
    const int m_base = (wid >> 1) * 32, n_base = (wid & 1) * 32;
    float acc1[2][4][4] = {}, acc2[2][4][4] = {};
    for (int ch = 0; ch < 16; ch++) {
        int ko = ch * 64;
        stage<8>(sm+OD_A1H, 72, g_A_hi   + (size_t)(r0)*N_ + ko, N_, 128);
        stage<8>(sm+OD_A1L, 72, g_A_lo   + (size_t)(r0)*N_ + ko, N_, 128);
        stage<8>(sm+OD_A2H, 72, g_sup_hi + (size_t)(r0)*N_ + ko, N_, 128);
        stage<8>(sm+OD_A2L, 72, g_sup_lo + (size_t)(r0)*N_ + ko, N_, 128);
        stage<8>(sm+OD_BH,  72, g_x_hi + ((size_t)bt*N_ + ko)*C_, C_, 64);
        stage<8>(sm+OD_BL,  72, g_x_lo + ((size_t)bt*N_ + ko)*C_, C_, 64);
        __syncthreads();
        warp_mma<2>(acc1, sm+OD_A1H, sm+OD_A1L, 72, sm+OD_BH, sm+OD_BL, 72,
                    m_base, n_base, lane);
        warp_mma<2>(acc2, sm+OD_A2H, sm+OD_A2L, 72, sm+OD_BH, sm+OD_BL, 72,
                    m_base, n_base, lane);
        __syncthreads();
    }
    const float g = gamma[0];
#pragma unroll
    for (int mi = 0; mi < 2; mi++)
#pragma unroll
        for (int j = 0; j < 4; j++) {
            int r = r0 + m_base + mi*16 + (lane >> 2);
            int c = n_base + j*8 + (lane & 3)*2;
            size_t i0 = ((size_t)bt*N_ + r)*C_ + c;
            size_t i8 = ((size_t)bt*N_ + r + 8)*C_ + c;
            out[i0]   = g * fmaxf(acc1[mi][j][0], 0.f);
            out[i0+1] = g * fmaxf(acc1[mi][j][1], 0.f);
            out[i8]   = g * fmaxf(acc1[mi][j][2], 0.f);
            out[i8+1] = g * fmaxf(acc1[mi][j][3], 0.f);
            g_xg[i0]   = acc2[mi][j][0];
            g_xg[i0+1] = acc2[mi][j][1];
            g_xg[i8]   = acc2[mi][j][2];
            g_xg[i8+1] = acc2[mi][j][3];
        }
}

// ======================= bias (fp32, split-K) ===============================
__global__ void k_bias_part(const float* __restrict__ bp) {
    __shared__ float As[16][68];
    __shared__ float Bs[16][68];
    int tid = threadIdx.x, tx = tid & 15, ty = tid >> 4;
    int m0 = blockIdx.x * 64, kb = blockIdx.y * 128;
    float acc[4][4] = {};
    for (int k0 = kb; k0 < kb + 128; k0 += 16) {
#pragma unroll
        for (int e = tid; e < 1024; e += 256) {
            int mm = e >> 4, kk = e & 15;
            As[kk][mm] = g_supports[(size_t)(m0+mm)*N_ + k0 + kk];
        }
#pragma unroll
        for (int e = tid; e < 1024; e += 256) {
            int kk = e >> 6, nn = e & 63;
            Bs[kk][nn] = bp[(size_t)(k0+kk)*C_ + nn];
        }
        __syncthreads();
#pragma unroll
        for (int k = 0; k < 16; k++) {
            float4 ra = *(const float4*)&As[k][ty<<2];
            float4 rb = *(const float4*)&Bs[k][tx<<2];
            float a[4] = {ra.x, ra.y, ra.z, ra.w};
            float b[4] = {rb.x, rb.y, rb.z, rb.w};
#pragma unroll
            for (int i = 0; i < 4; i++)
#pragma unroll
                for (int j = 0; j < 4; j++) acc[i][j] += a[i]*b[j];
        }
        __syncthreads();
    }
    float* dst = g_bias_part + (size_t)blockIdx.y * N_ * C_;
#pragma unroll
    for (int i = 0; i < 4; i++)
#pragma unroll
        for (int j = 0; j < 4; j++)
            dst[(size_t)(m0+(ty<<2)+i)*C_ + (tx<<2) + j] = acc[i][j];
}
__global__ void k_bias_red() {
    int i = blockIdx.x * 256 + threadIdx.x;
    float s = 0.f;
#pragma unroll
    for (int c = 0; c < 8; c++) s += g_bias_part[(size_t)c*N_*C_ + i];
    g_bias[i] = s;
}

// ---------------- gconv: out += alpha*relu(xg[:,n,:] @ W[n] + bias[n]) ------
__global__ void k_gconv(const float* __restrict__ alpha,
                        float* __restrict__ out) {
    int n = blockIdx.x, tid = threadIdx.x;
    __shared__ float Ws[64*64];
    __shared__ float Xs[96][64];
    __shared__ float bs[64];
#pragma unroll
    for (int e = tid; e < 4096; e += 256) Ws[e] = g_weights[(size_t)n*4096 + e];
    if (tid < 64) bs[tid] = g_bias[(size_t)n*64 + tid];
#pragma unroll
    for (int e = tid; e < 96*64; e += 256) {
        int r = e >> 6, c = e & 63;
        Xs[r][c] = g_xg[((size_t)r*N_ + n)*C_ + c];
    }
    __syncthreads();
    float al = alpha[0];
    int o = tid & 63, rg = tid >> 6;
    for (int r = rg; r < 96; r += 4) {
        float acc = bs[o];
#pragma unroll
        for (int i = 0; i < 64; i++) acc = fmaf(Xs[r][i], Ws[i*64 + o], acc);
        size_t idx = ((size_t)r*N_ + n)*C_ + o;
        out[idx] += al * fmaxf(acc, 0.f);
    }
}

// ======================= launch =============================================
extern "C" void kernel_launch(void* const* d_in, const int* in_sizes, int n_in,
                              void* d_out, int out_size) {
    (void)in_sizes; (void)n_in; (void)out_size;
    const float* x     = (const float*)d_in[0];
    const float* e1    = (const float*)d_in[1];
    const float* e2    = (const float*)d_in[2];
    const float* A_sym = (const float*)d_in[3];
    const float* wp    = (const float*)d_in[4];
    const float* bp    = (const float*)d_in[5];
    const float* alpha = (const float*)d_in[6];
    const float* beta  = (const float*)d_in[7];
    const float* gamma = (const float*)d_in[8];
    float* out = (float*)d_out;

    cudaFuncSetAttribute(k_weights_mma, cudaFuncAttributeMaxDynamicSharedMemorySize, SMW_BYTES);
    cudaFuncSetAttribute(k_score_mma,   cudaFuncAttributeMaxDynamicSharedMemorySize, SMW_BYTES);
    cudaFuncSetAttribute(k_sa_mma,      cudaFuncAttributeMaxDynamicSharedMemorySize, SMS_BYTES);
    cudaFuncSetAttribute(k_dual_mma,    cudaFuncAttributeMaxDynamicSharedMemorySize, SMD_BYTES);

    k_supports   <<<dim3(N_/16, N_/16), dim3(16,16)>>>(e1, e2);
    k_softmaxA   <<<N_, 256>>>(A_sym);
    k_cvt_x      <<<dim3(N_/64, BT_), 256>>>(x);
    k_cvt_wp     <<<(1024*4096)/(256*4), 256>>>(wp);
    k_weights_mma<<<dim3(32, 8), 256, SMW_BYTES>>>();
    k_bias_part  <<<dim3(N_/64, 8), 256>>>(bp);
    k_bias_red   <<<(N_*C_)/256, 256>>>();
    k_score_mma  <<<dim3(8, 8, BT_), 256, SMW_BYTES>>>();
    k_softmax_t  <<<(B_*N_*N_)/256, 256>>>();
    k_dual_mma   <<<dim3(8, BT_), 256, SMD_BYTES>>>(gamma, out);
    k_sa_mma     <<<dim3(8, BT_), 256, SMS_BYTES>>>(beta, out);
    k_gconv      <<<N_, 256>>>(alpha, out);
}